// round 15
// baseline (speedup 1.0000x reference)
#include <cuda_runtime.h>
#include <cstdint>

// Delta modulation encoder: 512 independent serial scans of length 131072.
// Bit-exact fp32 replication of:
//   err = fl(x_t - r); p = err>0.1; n = err<-0.1; spike = p-n; r = fl(r + spike*0.1)
//
// R14 lesson: I/O warps sharing compute SMSPs regress (hi-wid arbiter priority).
// R10 lesson: interleave via separate asm blocks never interleaves in SASS.
// R15: ONE fused asm block running TWO independent sequences' steps with
// manually interleaved instructions (A/B pairs). Chain latency of each seq
// hides behind the other's ops -> period ~ issue/pipe bound per PAIR.
// Shell = R11 (best): 128 blocks, single I/O warp (own SMSP), err-carry with
// spike conversion offloaded to the I/O warp. 2 compute warps x 2 seqs each.

constexpr int T_LEN = 131072;
constexpr int NSEQ  = 512;            // 64 * 8
constexpr int SEQ_B = 4;              // sequences (rows) per block
constexpr int TILE  = 128;            // time steps per tile
constexpr int NT    = T_LEN / TILE;   // 1024 tiles
constexpr int ROWF  = TILE + 4;       // 132 floats = 528B stride
constexpr int NBUF  = 3;              // input ring: t, t+1 resident, t+2 in flight
constexpr int GRP   = TILE / 4;       // 32 float4 groups per tile
constexpr int NTHREADS = 96;          // 2 compute warps (2 seqs each) + 1 I/O warp

struct DMCarry {
    float rr;               // resolved recon
    float cu, cd;           // fl(rr+0.1f), fl(rr-0.1f)
    float Eu, Ed, Ez;       // x_{t+1} - {cu, cd, rr}
};

// TWO elements (one per sequence), fused + manually interleaved in one asm
// block so SASS interleaving is guaranteed. Per sequence identical to the R11
// 10-op step (bit-exact). eA/eB = err_t, xnA/xnB = x[t+2]; returns err_{t+1}.
__device__ __forceinline__ void dm_step2(float eA, float eB,
                                         DMCarry& sA, DMCarry& sB,
                                         float xnA, float xnB,
                                         float& eoA, float& eoB) {
    asm("{\n\t"
        ".reg .pred pA, nA, pB, nB;\n\t"
        ".reg .f32 t1A, t2A, t1B, t2B;\n\t"
        "setp.gt.f32 pA, %14, 0f3DCCCCCD;\n\t"
        "setp.lt.f32 nA, %14, 0fBDCCCCCD;\n\t"
        "setp.gt.f32 pB, %15, 0f3DCCCCCD;\n\t"
        "setp.lt.f32 nB, %15, 0fBDCCCCCD;\n\t"
        "selp.f32 t1A, %5, %6, nA;\n\t"          // nA ? EdA : EzA
        "selp.f32 t1B, %11, %12, nB;\n\t"
        "selp.f32 %0, %4, t1A, pA;\n\t"          // eoA = pA ? EuA : t1A
        "selp.f32 %1, %10, t1B, pB;\n\t"
        "selp.f32 t2A, %3, %2, nA;\n\t"          // nA ? cdA : rrA
        "selp.f32 t2B, %9, %8, nB;\n\t"
        "selp.f32 %2, %7, t2A, pA;\n\t"          // rrA' = pA ? cuA : t2A
        "selp.f32 %8, %13, t2B, pB;\n\t"
        "add.f32 %7, %2, 0f3DCCCCCD;\n\t"        // cuA' = fl(rrA' + 0.1f)
        "add.f32 %13, %8, 0f3DCCCCCD;\n\t"
        "add.f32 %3, %2, 0fBDCCCCCD;\n\t"        // cdA' = fl(rrA' - 0.1f)
        "add.f32 %9, %8, 0fBDCCCCCD;\n\t"
        "sub.f32 %4, %16, %7;\n\t"               // EuA' = fl(xnA - cuA')
        "sub.f32 %10, %17, %13;\n\t"
        "sub.f32 %5, %16, %3;\n\t"               // EdA'
        "sub.f32 %11, %17, %9;\n\t"
        "sub.f32 %6, %16, %2;\n\t"               // EzA'
        "sub.f32 %12, %17, %8;\n\t"
        "}"
        : "=f"(eoA), "=f"(eoB),
          "+f"(sA.rr), "+f"(sA.cd), "+f"(sA.Eu), "+f"(sA.Ed), "+f"(sA.Ez), "+f"(sA.cu),
          "+f"(sB.rr), "+f"(sB.cd), "+f"(sB.Eu), "+f"(sB.Ed), "+f"(sB.Ez), "+f"(sB.cu)
        : "f"(eA), "f"(eB), "f"(xnA), "f"(xnB));
}

__device__ __forceinline__ void cp_async16(uint32_t dst_smem, const void* src) {
    asm volatile("cp.async.cg.shared.global [%0], [%1], 16;"
                 :: "r"(dst_smem), "l"(src));
}
__device__ __forceinline__ void cp_commit() {
    asm volatile("cp.async.commit_group;" ::: "memory");
}
__device__ __forceinline__ void cp_wait1() {
    asm volatile("cp.async.wait_group 1;" ::: "memory");
}
__device__ __forceinline__ void bar1() {
    asm volatile("bar.sync 1, %0;" :: "n"(NTHREADS) : "memory");
}
__device__ __forceinline__ void bar2() {
    asm volatile("bar.sync 2, %0;" :: "n"(NTHREADS) : "memory");
}

__global__ __launch_bounds__(NTHREADS, 1)
void DeltaModulationEncoder_kernel(const float* __restrict__ x,
                                   float* __restrict__ out) {
    __shared__ __align__(16) float sin_buf[NBUF][SEQ_B * ROWF];  // input ring
    __shared__ __align__(16) float serr[2][SEQ_B * ROWF];        // err staging

    const int tid  = threadIdx.x;
    const int warp = tid >> 5;
    const int lane = tid & 31;
    const int seqbase = blockIdx.x * SEQ_B;

    if (warp == 2) {
        // ───────────────── I/O warp (own SMSP, as in R11) ─────────────────
        const size_t rowstride = (size_t)T_LEN * 4;
        const char* gsrc = (const char*)(x + (size_t)seqbase * T_LEN) + lane * 16;
        char*       gdst = (char*)(out + (size_t)seqbase * T_LEN) + lane * 16;

        uint32_t sin_addr[NBUF];
#pragma unroll
        for (int b = 0; b < NBUF; b++)
            sin_addr[b] = (uint32_t)__cvta_generic_to_shared(&sin_buf[b][0])
                        + (uint32_t)(lane * 16);

        // Convert err tile -> spikes (exact: +-1.0f / +0.0f), STG directly.
        auto flush_tile = [&](int tp) {
            const float* sb = &serr[tp & 1][0] + lane * 4;
            char* g = gdst + (size_t)tp * TILE * 4;
#pragma unroll
            for (int i = 0; i < SEQ_B; i++) {
                float4 e = *(const float4*)(sb + i * ROWF);
                float4 sp;
                sp.x = (e.x > 0.1f) ? 1.0f : ((e.x < -0.1f) ? -1.0f : 0.0f);
                sp.y = (e.y > 0.1f) ? 1.0f : ((e.y < -0.1f) ? -1.0f : 0.0f);
                sp.z = (e.z > 0.1f) ? 1.0f : ((e.z < -0.1f) ? -1.0f : 0.0f);
                sp.w = (e.w > 0.1f) ? 1.0f : ((e.w < -0.1f) ? -1.0f : 0.0f);
                *(float4*)(g + (size_t)i * rowstride) = sp;
            }
        };

#pragma unroll
        for (int t0 = 0; t0 < 2; t0++) {
            const char* g = gsrc + (size_t)t0 * TILE * 4;
            const uint32_t s = sin_addr[t0];
#pragma unroll
            for (int i = 0; i < SEQ_B; i++)
                cp_async16(s + (uint32_t)(i * ROWF * 4), g + (size_t)i * rowstride);
            cp_commit();
        }

        int slot_w = 2;
        for (int t = 0; t < NT; ++t) {
            if (t + 2 < NT) {
                const char* g = gsrc + (size_t)(t + 2) * TILE * 4;
                const uint32_t s = sin_addr[slot_w];
#pragma unroll
                for (int i = 0; i < SEQ_B; i++)
                    cp_async16(s + (uint32_t)(i * ROWF * 4), g + (size_t)i * rowstride);
            }
            cp_commit();
            cp_wait1();                 // tiles t, t+1 resident
            bar1();                     // release compute for tile t

            if (t > 0) flush_tile(t - 1);

            bar2();                     // serr[(t-1)&1] reusable; tile t errs visible
            slot_w = (slot_w + 1 == NBUF) ? 0 : slot_w + 1;
        }
        flush_tile(NT - 1);
    } else {
        // ─────────── compute warps 0-1: TWO interleaved sequences each ───────────
        // Warp w owns rows 2w (A) and 2w+1 (B); lanes 1-31 duplicate lane 0.
        const int rA = warp * 2;
        const int rB = warp * 2 + 1;
        const bool writer = (lane == 0);

        DMCarry sA, sB;
        float eA, eB;
        int s0 = 0;
        for (int t = 0; t < NT; ++t) {
            const int s1 = (s0 + 1 == NBUF) ? 0 : s0 + 1;
            bar1();                     // tiles t (slot s0), t+1 (slot s1) resident

            if (t == 0) {               // recon r0 = 0, both sequences
                const float a0 = sin_buf[0][rA * ROWF + 0];
                const float a1 = sin_buf[0][rA * ROWF + 1];
                eA = a0; sA.rr = 0.0f; sA.cu = 0.1f; sA.cd = -0.1f;
                sA.Eu = a1 - 0.1f; sA.Ed = a1 + 0.1f; sA.Ez = a1;
                const float b0 = sin_buf[0][rB * ROWF + 0];
                const float b1 = sin_buf[0][rB * ROWF + 1];
                eB = b0; sB.rr = 0.0f; sB.cu = 0.1f; sB.cd = -0.1f;
                sB.Eu = b1 - 0.1f; sB.Ed = b1 + 0.1f; sB.Ez = b1;
            }

            const float4* bkA  = (const float4*)(&sin_buf[s0][0] + rA * ROWF);
            const float4* bkA1 = (const float4*)(&sin_buf[s1][0] + rA * ROWF);
            const float4* bkB  = (const float4*)(&sin_buf[s0][0] + rB * ROWF);
            const float4* bkB1 = (const float4*)(&sin_buf[s1][0] + rB * ROWF);
            float4* soA = (float4*)(&serr[t & 1][0] + rA * ROWF);
            float4* soB = (float4*)(&serr[t & 1][0] + rB * ROWF);

            float4 curA = bkA[0], nxtA = bkA[1];
            float4 curB = bkB[0], nxtB = bkB[1];
#pragma unroll
            for (int g = 0; g < GRP; ++g) {
                // group g+2 (peeks into tile t+1 for g >= GRP-2; past the last
                // tile this is stale smem feeding only never-output candidates)
                const float4 nnA = (g < GRP - 2) ? bkA[g + 2] : bkA1[g - (GRP - 2)];
                const float4 nnB = (g < GRP - 2) ? bkB[g + 2] : bkB1[g - (GRP - 2)];

                float4 evA, evB;             // err_t outputs for both rows
                evA.x = eA; evB.x = eB;
                dm_step2(eA, eB, sA, sB, curA.z, curB.z, eA, eB);
                evA.y = eA; evB.y = eB;
                dm_step2(eA, eB, sA, sB, curA.w, curB.w, eA, eB);
                evA.z = eA; evB.z = eB;
                dm_step2(eA, eB, sA, sB, nxtA.x, nxtB.x, eA, eB);
                evA.w = eA; evB.w = eB;
                dm_step2(eA, eB, sA, sB, nxtA.y, nxtB.y, eA, eB);
                if (writer) {               // predicated STS.128 x2, lane 0
                    soA[g] = evA;
                    soB[g] = evB;
                }

                curA = nxtA; nxtA = nnA;
                curB = nxtB; nxtB = nnB;
            }
            bar2();                     // hand serr[t&1] to the I/O warp
            s0 = s1;
        }
    }
}

extern "C" void kernel_launch(void* const* d_in, const int* in_sizes, int n_in,
                              void* d_out, int out_size) {
    (void)in_sizes; (void)n_in; (void)out_size;
    const float* x = (const float*)d_in[0];
    float* out     = (float*)d_out;

    // 128 blocks x (2 compute warps x 2 fused-interleaved seqs + 1 I/O warp).
    DeltaModulationEncoder_kernel<<<NSEQ / SEQ_B, NTHREADS>>>(x, out);
}

// round 16
// speedup vs baseline: 1.0829x; 1.0829x over previous
#include <cuda_runtime.h>
#include <cstdint>

// Delta modulation encoder: 512 independent serial scans of length 131072.
// Bit-exact fp32 replication of:
//   err = fl(x_t - r); p = err>0.1; n = err<-0.1; spike = p-n; r = fl(r + spike*0.1)
//
// R15 lesson: fused pairs run at exactly the PIPE-THROUGHPUT bound (44 = 2x22);
// our setp/selp/add fp step is single-pipe (fma) at rt=2 -> 22 cyc/step floor.
// R16: two-pipe mix. R12's integer-mask step (bit-exact, verified) splits
// 7 fma-pipe (FFMA/FADD/FSUB) + 6 alu-pipe (SHF/LOP3) ops. Fused 2-seq pair:
// 14 fma / 12 alu -> ~28 cyc/pair = ~14 cyc/step. Shell = R11 (best): 128
// blocks, 1 I/O warp on its own SMSP, err-bits staged, spikes made by I/O warp.

constexpr int T_LEN = 131072;
constexpr int NSEQ  = 512;            // 64 * 8
constexpr int SEQ_B = 4;              // sequences (rows) per block
constexpr int TILE  = 128;            // time steps per tile
constexpr int NT    = T_LEN / TILE;   // 1024 tiles
constexpr int ROWF  = TILE + 8;       // 136 floats: 128 data + 8 pad (next tile head)
constexpr int NBUF  = 3;              // input ring: t, t+1 resident, t+2 in flight
constexpr int GRP   = TILE / 4;       // 32 float4 groups per tile
constexpr int NTHREADS = 96;          // 2 compute warps (2 seqs each) + 1 I/O warp

struct DMC {
    uint32_t rr;            // recon bits
    uint32_t cu, cd;        // bits of fl(rr+0.1f), fl(rr-0.1f)
    uint32_t Eu, Ed, Ez;    // bits of x_{t+1} - {cu, cd, rr}
};

__device__ __forceinline__ uint32_t bitsel(uint32_t z, uint32_t d, uint32_t m) {
    return z ^ ((z ^ d) & m);          // m ? d : z   (one LOP3)
}

// One element, int-mask form (R12, bit-exact: sign-FFMA guard handles strict
// ties at e == +-0.1f via exact cancellation to +0). 13 ops: 7 fma-pipe,
// 6 alu-pipe, zero predicates.
__device__ __forceinline__ uint32_t dm_step(uint32_t e, DMC& s, float xnn) {
    const float BIG = __uint_as_float(0x7F000000u);   // 2^127
    const float THB = __uint_as_float(0x7D4CCCCDu);   // 0.1f * 2^127

    const float ef = __uint_as_float(e);
    const float mu = __fmaf_rn(ef, -BIG, THB);        // sign(0.1 - e)
    const float md = __fmaf_rn(ef,  BIG, THB);        // sign(0.1 + e)
    const uint32_t su = (uint32_t)((int32_t)__float_as_uint(mu) >> 31); // -1 iff e>0.1
    const uint32_t sd = (uint32_t)((int32_t)__float_as_uint(md) >> 31); // -1 iff e<-0.1

    const uint32_t en = bitsel(bitsel(s.Ez, s.Ed, sd), s.Eu, su);  // err'
    const uint32_t rn = bitsel(bitsel(s.rr, s.cd, sd), s.cu, su);  // rr'

    const float rrf = __uint_as_float(rn);
    const float cuf = rrf + 0.1f;                     // fl(rr' + 0.1f)
    const float cdf = rrf - 0.1f;                     // fl(rr' - 0.1f)
    s.rr = rn;
    s.cu = __float_as_uint(cuf);
    s.cd = __float_as_uint(cdf);
    s.Eu = __float_as_uint(xnn - cuf);
    s.Ed = __float_as_uint(xnn - cdf);
    s.Ez = __float_as_uint(xnn - rrf);
    return en;
}

__device__ __forceinline__ void dm_init(uint32_t& e, DMC& s, const float* rowp) {
    const float x0 = rowp[0];
    const float x1 = rowp[1];
    e     = __float_as_uint(x0);       // err_0 = fl(x0 - 0)
    s.rr  = 0u;                        // +0.0f
    s.cu  = 0x3DCCCCCDu;               //  0.1f
    s.cd  = 0xBDCCCCCDu;               // -0.1f
    s.Eu  = __float_as_uint(x1 - 0.1f);
    s.Ed  = __float_as_uint(x1 + 0.1f);
    s.Ez  = __float_as_uint(x1);
}

__device__ __forceinline__ void cp_async16(uint32_t dst_smem, const void* src) {
    asm volatile("cp.async.cg.shared.global [%0], [%1], 16;"
                 :: "r"(dst_smem), "l"(src));
}
__device__ __forceinline__ void cp_commit() {
    asm volatile("cp.async.commit_group;" ::: "memory");
}
__device__ __forceinline__ void cp_wait1() {
    asm volatile("cp.async.wait_group 1;" ::: "memory");
}
__device__ __forceinline__ void bar1() {
    asm volatile("bar.sync 1, %0;" :: "n"(NTHREADS) : "memory");
}
__device__ __forceinline__ void bar2() {
    asm volatile("bar.sync 2, %0;" :: "n"(NTHREADS) : "memory");
}

__global__ __launch_bounds__(NTHREADS, 1)
void DeltaModulationEncoder_kernel(const float* __restrict__ x,
                                   float* __restrict__ out) {
    __shared__ __align__(16) float sin_buf[NBUF][SEQ_B * ROWF];  // ~6.5 KB
    __shared__ __align__(16) float serr[2][SEQ_B * ROWF];        // ~4.4 KB

    const int tid  = threadIdx.x;
    const int warp = tid >> 5;
    const int lane = tid & 31;
    const int seqbase = blockIdx.x * SEQ_B;

    if (warp == 2) {
        // ───────────────── I/O warp (own SMSP) ─────────────────
        const size_t rowstride = (size_t)T_LEN * 4;
        const char* gsrc = (const char*)(x + (size_t)seqbase * T_LEN) + lane * 16;
        char*       gdst = (char*)(out + (size_t)seqbase * T_LEN) + lane * 16;

        uint32_t sin_addr[NBUF];
#pragma unroll
        for (int b = 0; b < NBUF; b++)
            sin_addr[b] = (uint32_t)__cvta_generic_to_shared(&sin_buf[b][0])
                        + (uint32_t)(lane * 16);

        // Stage tile t into slot: 4 rows x 512B, plus 32B pad per row holding
        // the head of tile t+1 (clamped at the end; pad only feeds candidates
        // of never-output steps there).
        auto issue_tile = [&](int t, int slot) {
            const char* g = gsrc + (size_t)t * TILE * 4;
            const int tp = (t + 1 < NT) ? t + 1 : t;      // clamp: safe source
            const char* gp = gsrc + (size_t)tp * TILE * 4;
            const uint32_t s = sin_addr[slot];
#pragma unroll
            for (int i = 0; i < SEQ_B; i++)
                cp_async16(s + (uint32_t)(i * ROWF * 4), g + (size_t)i * rowstride);
            if (lane < 2) {
#pragma unroll
                for (int i = 0; i < SEQ_B; i++)
                    cp_async16(s + (uint32_t)(i * ROWF * 4 + TILE * 4),
                               gp + (size_t)i * rowstride);
            }
        };

        // Convert err tile -> spikes (exact: +-1.0f / +0.0f), STG directly.
        auto flush_tile = [&](int tp) {
            const float* sb = &serr[tp & 1][0] + lane * 4;
            char* g = gdst + (size_t)tp * TILE * 4;
#pragma unroll
            for (int i = 0; i < SEQ_B; i++) {
                float4 e = *(const float4*)(sb + i * ROWF);
                float4 sp;
                sp.x = (e.x > 0.1f) ? 1.0f : ((e.x < -0.1f) ? -1.0f : 0.0f);
                sp.y = (e.y > 0.1f) ? 1.0f : ((e.y < -0.1f) ? -1.0f : 0.0f);
                sp.z = (e.z > 0.1f) ? 1.0f : ((e.z < -0.1f) ? -1.0f : 0.0f);
                sp.w = (e.w > 0.1f) ? 1.0f : ((e.w < -0.1f) ? -1.0f : 0.0f);
                *(float4*)(g + (size_t)i * rowstride) = sp;
            }
        };

        issue_tile(0, 0); cp_commit();
        issue_tile(1, 1); cp_commit();

        int slot_w = 2;
        for (int t = 0; t < NT; ++t) {
            if (t + 2 < NT) issue_tile(t + 2, slot_w);
            cp_commit();
            cp_wait1();                 // tiles t, t+1 resident
            bar1();                     // release compute for tile t

            if (t > 0) flush_tile(t - 1);

            bar2();                     // serr[(t-1)&1] reusable; tile t errs visible
            slot_w = (slot_w + 1 == NBUF) ? 0 : slot_w + 1;
        }
        flush_tile(NT - 1);
    } else {
        // ─────────── compute warps 0-1: TWO interleaved sequences each ───────────
        // Warp w owns rows 2w (A) and 2w+1 (B). Independent C++ dataflow:
        // ptxas schedules the pair onto both pipes. Lanes 1-31 duplicate lane 0.
        const int rA = warp * 2;
        const int rB = warp * 2 + 1;
        const bool writer = (lane == 0);

        DMC sA, sB;
        uint32_t eA, eB;
        int s0 = 0;
        for (int t = 0; t < NT; ++t) {
            const int s1 = (s0 + 1 == NBUF) ? 0 : s0 + 1;
            bar1();                     // tiles t (slot s0), t+1 (slot s1) resident

            if (t == 0) {
                dm_init(eA, sA, &sin_buf[0][rA * ROWF]);
                dm_init(eB, sB, &sin_buf[0][rB * ROWF]);
            }

            const float4* bkA = (const float4*)(&sin_buf[s0][0] + rA * ROWF);
            const float4* bkB = (const float4*)(&sin_buf[s0][0] + rB * ROWF);
            uint4* soA = (uint4*)(&serr[t & 1][0] + rA * ROWF);
            uint4* soB = (uint4*)(&serr[t & 1][0] + rB * ROWF);

            float4 curA = bkA[0], nxtA = bkA[1];
            float4 curB = bkB[0], nxtB = bkB[1];
#pragma unroll 8
            for (int g = 0; g < GRP; ++g) {
                // Pad makes bk[g+2] always valid (g+2 <= GRP+1 -> <= ROWF/4-1).
                const float4 nnA = bkA[g + 2];
                const float4 nnB = bkB[g + 2];

                uint4 evA, evB;              // err_t bits (outputs)
                evA.x = eA; evB.x = eB;
                eA = dm_step(eA, sA, curA.z); eB = dm_step(eB, sB, curB.z);
                evA.y = eA; evB.y = eB;
                eA = dm_step(eA, sA, curA.w); eB = dm_step(eB, sB, curB.w);
                evA.z = eA; evB.z = eB;
                eA = dm_step(eA, sA, nxtA.x); eB = dm_step(eB, sB, nxtB.x);
                evA.w = eA; evB.w = eB;
                eA = dm_step(eA, sA, nxtA.y); eB = dm_step(eB, sB, nxtB.y);
                if (writer) {                // predicated STS.128 x2, lane 0
                    soA[g] = evA;
                    soB[g] = evB;
                }

                curA = nxtA; nxtA = nnA;
                curB = nxtB; nxtB = nnB;
            }
            bar2();                     // hand serr[t&1] to the I/O warp
            s0 = s1;
        }
    }
}

extern "C" void kernel_launch(void* const* d_in, const int* in_sizes, int n_in,
                              void* d_out, int out_size) {
    (void)in_sizes; (void)n_in; (void)out_size;
    const float* x = (const float*)d_in[0];
    float* out     = (float*)d_out;

    // 128 blocks x (2 compute warps x 2 fused sequences + 1 I/O warp).
    DeltaModulationEncoder_kernel<<<NSEQ / SEQ_B, NTHREADS>>>(x, out);
}

// round 17
// speedup vs baseline: 1.8484x; 1.7069x over previous
#include <cuda_runtime.h>
#include <cstdint>

// Delta modulation encoder: 512 independent serial scans of length 131072.
// Bit-exact fp32 replication of:
//   err = fl(x_t - r); p = err>0.1; n = err<-0.1; spike = p-n; r = fl(r + spike*0.1)
//
// R16 lesson: wall = T x single-step period; multi-seq interleave can't win.
// Floor = max(chain latency, fma-pipe ops x 2). selp form: 11 fma ops & 21-cyc
// chain -> 22. R17 step breaks both:
//   p = FSETP.GT.ABS(err, 0.1)          (ONE compare; strict; fma pipe)
//   m = err>>31 (SHR, alu), t = LOP3-bitsel(Eu, Ed, m)  (alu)
//   err' = SELP(t, Ez, p)               -> chain ~17 cyc
//   fma-pipe ops/step = 8 (FSETP, 2 SELP, 2 FADD, 3 FSUB) -> throughput 16
// Shell identical to R11 (best): 128 blocks x 4 compute warps + 1 I/O warp;
// err staged to smem; I/O warp converts err->spike (exact) and does all gmem.

constexpr int T_LEN = 131072;
constexpr int NSEQ  = 512;            // 64 * 8
constexpr int SEQ_B = 4;              // sequences (rows) per block, one per compute warp
constexpr int TILE  = 128;            // time steps per lane per tile
constexpr int NT    = T_LEN / TILE;   // 1024 tiles
constexpr int ROWF  = TILE + 4;       // 132 floats = 528B stride
constexpr int NBUF  = 3;              // input ring: t, t+1 resident, t+2 in flight
constexpr int GRP   = TILE / 4;       // 32 float4 groups per tile
constexpr int NTHREADS = 160;         // 4 compute warps + 1 I/O warp

struct DMCarry {
    float rr;               // resolved recon
    float cu, cd;           // fl(rr+0.1f), fl(rr-0.1f)
    float Eu, Ed, Ez;       // x_{t+1} - {cu, cd, rr}
};

__device__ __forceinline__ float fbitsel(float a, float b, uint32_t m) {
    // m ? b : a, exact bit select (one LOP3; regs are untyped in SASS)
    const uint32_t ab = __float_as_uint(a);
    const uint32_t bb = __float_as_uint(b);
    return __uint_as_float(ab ^ ((ab ^ bb) & m));
}

// One element. e = err_t (input), xnn = x[t+2]. Returns err_{t+1}. Bit-exact:
//  - spike iff |err| > 0.1 STRICT (ties -> no spike), sign by err's sign bit
//    (|err|>0.1 excludes err==0, so the sign is always well-defined).
//  - candidate recons/errs computed with the reference's exact rounding order.
__device__ __forceinline__ float dm_step(float e, DMCarry& s, float xnn) {
    const uint32_t m = (uint32_t)((int32_t)__float_as_uint(e) >> 31); // -1 iff e<0
    const bool p = fabsf(e) > 0.1f;                 // FSETP.GT.ABS, one op

    const float t  = fbitsel(s.Eu, s.Ed, m);        // e>0 ? Eu : Ed
    const float en = p ? t : s.Ez;                  // err' (chain: ~17 cyc)

    const float rc = fbitsel(s.cu, s.cd, m);        // e>0 ? cu : cd
    const float rn = p ? rc : s.rr;                 // rr'

    s.rr = rn;
    s.cu = rn + 0.1f;                               // fl(rr' + 0.1f)
    s.cd = rn - 0.1f;                               // fl(rr' - 0.1f)
    s.Eu = xnn - s.cu;                              // fl(xnn - cu')
    s.Ed = xnn - s.cd;
    s.Ez = xnn - rn;
    return en;
}

__device__ __forceinline__ void cp_async16(uint32_t dst_smem, const void* src) {
    asm volatile("cp.async.cg.shared.global [%0], [%1], 16;"
                 :: "r"(dst_smem), "l"(src));
}
__device__ __forceinline__ void cp_commit() {
    asm volatile("cp.async.commit_group;" ::: "memory");
}
__device__ __forceinline__ void cp_wait1() {
    asm volatile("cp.async.wait_group 1;" ::: "memory");
}
__device__ __forceinline__ void bar1() {
    asm volatile("bar.sync 1, %0;" :: "n"(NTHREADS) : "memory");
}
__device__ __forceinline__ void bar2() {
    asm volatile("bar.sync 2, %0;" :: "n"(NTHREADS) : "memory");
}

__global__ __launch_bounds__(NTHREADS, 1)
void DeltaModulationEncoder_kernel(const float* __restrict__ x,
                                   float* __restrict__ out) {
    __shared__ __align__(16) float sin_buf[NBUF][SEQ_B * ROWF];  // input ring
    __shared__ __align__(16) float serr[2][SEQ_B * ROWF];        // err staging

    const int tid  = threadIdx.x;
    const int warp = tid >> 5;
    const int lane = tid & 31;
    const int seqbase = blockIdx.x * SEQ_B;

    if (warp == 4) {
        // ───────────────────────── I/O warp (own SMSP) ─────────────────────────
        const size_t rowstride = (size_t)T_LEN * 4;
        const char* gsrc = (const char*)(x + (size_t)seqbase * T_LEN) + lane * 16;
        char*       gdst = (char*)(out + (size_t)seqbase * T_LEN) + lane * 16;

        uint32_t sin_addr[NBUF];
#pragma unroll
        for (int b = 0; b < NBUF; b++)
            sin_addr[b] = (uint32_t)__cvta_generic_to_shared(&sin_buf[b][0])
                        + (uint32_t)(lane * 16);

        // Convert err tile -> spikes (exact: +-1.0f / +0.0f), STG directly.
        auto flush_tile = [&](int tp) {
            const float* sb = &serr[tp & 1][0] + lane * 4;
            char* g = gdst + (size_t)tp * TILE * 4;
#pragma unroll
            for (int i = 0; i < SEQ_B; i++) {
                float4 e = *(const float4*)(sb + i * ROWF);
                float4 sp;
                sp.x = (e.x > 0.1f) ? 1.0f : ((e.x < -0.1f) ? -1.0f : 0.0f);
                sp.y = (e.y > 0.1f) ? 1.0f : ((e.y < -0.1f) ? -1.0f : 0.0f);
                sp.z = (e.z > 0.1f) ? 1.0f : ((e.z < -0.1f) ? -1.0f : 0.0f);
                sp.w = (e.w > 0.1f) ? 1.0f : ((e.w < -0.1f) ? -1.0f : 0.0f);
                *(float4*)(g + (size_t)i * rowstride) = sp;
            }
        };

#pragma unroll
        for (int t0 = 0; t0 < 2; t0++) {
            const char* g = gsrc + (size_t)t0 * TILE * 4;
            const uint32_t s = sin_addr[t0];
#pragma unroll
            for (int i = 0; i < SEQ_B; i++)
                cp_async16(s + (uint32_t)(i * ROWF * 4), g + (size_t)i * rowstride);
            cp_commit();
        }

        int slot_w = 2;
        for (int t = 0; t < NT; ++t) {
            if (t + 2 < NT) {
                const char* g = gsrc + (size_t)(t + 2) * TILE * 4;
                const uint32_t s = sin_addr[slot_w];
#pragma unroll
                for (int i = 0; i < SEQ_B; i++)
                    cp_async16(s + (uint32_t)(i * ROWF * 4), g + (size_t)i * rowstride);
            }
            cp_commit();
            cp_wait1();                 // tiles t, t+1 resident
            bar1();                     // release compute for tile t

            if (t > 0) flush_tile(t - 1);

            bar2();                     // serr[(t-1)&1] reusable; tile t errs visible
            slot_w = (slot_w + 1 == NBUF) ? 0 : slot_w + 1;
        }
        flush_tile(NT - 1);
    } else {
        // ──────────────────── compute warps 0-3, 1 seq each ────────────────────
        const int row = warp;
        const bool writer = (lane == 0);

        DMCarry st;
        float e;
        int s0 = 0;
        for (int t = 0; t < NT; ++t) {
            const int s1 = (s0 + 1 == NBUF) ? 0 : s0 + 1;
            bar1();                     // tiles t (slot s0), t+1 (slot s1) resident

            if (t == 0) {               // recon r0 = 0
                const float x0 = sin_buf[0][row * ROWF + 0];
                const float x1 = sin_buf[0][row * ROWF + 1];
                e      = x0;            // err_0 = fl(x0 - 0)
                st.rr  = 0.0f;
                st.cu  = 0.1f;          // fl(0 + 0.1f)
                st.cd  = -0.1f;         // fl(0 - 0.1f)
                st.Eu  = x1 - 0.1f;
                st.Ed  = x1 + 0.1f;
                st.Ez  = x1;
            }

            const float4* bk  = (const float4*)(&sin_buf[s0][0] + row * ROWF);
            const float4* bk1 = (const float4*)(&sin_buf[s1][0] + row * ROWF);
            float4* so = (float4*)(&serr[t & 1][0] + row * ROWF);

            float4 cur = bk[0];
            float4 nxt = bk[1];
#pragma unroll
            for (int g = 0; g < GRP; ++g) {
                // group g+2 (peeks into tile t+1 for g >= GRP-2; past the last
                // tile this is stale smem feeding only never-output candidates)
                const float4 nn = (g < GRP - 2) ? bk[g + 2] : bk1[g - (GRP - 2)];

                float4 ev;                       // err_t values (outputs)
                ev.x = e; e = dm_step(e, st, cur.z);
                ev.y = e; e = dm_step(e, st, cur.w);
                ev.z = e; e = dm_step(e, st, nxt.x);
                ev.w = e; e = dm_step(e, st, nxt.y);
                if (writer) so[g] = ev;          // predicated STS.128, lane 0

                cur = nxt;
                nxt = nn;
            }
            bar2();                     // hand serr[t&1] to the I/O warp
            s0 = s1;
        }
    }
}

extern "C" void kernel_launch(void* const* d_in, const int* in_sizes, int n_in,
                              void* d_out, int out_size) {
    (void)in_sizes; (void)n_in; (void)out_size;
    const float* x = (const float*)d_in[0];
    float* out     = (float*)d_out;

    // 128 blocks x (4 compute warps + 1 I/O warp), 1 sequence per compute warp.
    DeltaModulationEncoder_kernel<<<NSEQ / SEQ_B, NTHREADS>>>(x, out);
}